// round 1
// baseline (speedup 1.0000x reference)
#include <cuda_runtime.h>

#define N_NODES 50000
#define E_EDGES 1600000
#define D_FEAT  128
#define K_SEG   16

#define EDGE_BLOCKS 1184
#define EDGE_THREADS 256
#define EDGE_WARPS_PER_BLOCK (EDGE_THREADS / 32)
#define TOTAL_EDGE_WARPS (EDGE_BLOCKS * EDGE_WARPS_PER_BLOCK)

// Scratch (no allocations allowed in kernel_launch)
__device__ float g_S[N_NODES * K_SEG];                 // softmax probabilities
__device__ int   g_idx_is64;                           // 1 if edge_index is int64
__device__ float g_partial[EDGE_BLOCKS * 2 * K_SEG];   // per-block [assoc(16), m(16)]

// ---------------------------------------------------------------------------
// Detect edge-index dtype. int32 data read as int64 yields lo + hi*2^32 with
// hi = next (nonzero w.h.p.) index -> huge values. Real int64 entries are all
// in [0, N_NODES).
// ---------------------------------------------------------------------------
__global__ void detect_idx_kernel(const void* __restrict__ ei_raw) {
    const long long* p = (const long long*)ei_raw;
    int is64 = 1;
    for (int i = 0; i < 64; i++) {
        long long v = p[i];
        if (v < 0 || v >= (long long)N_NODES) { is64 = 0; break; }
    }
    g_idx_is64 = is64;
}

// ---------------------------------------------------------------------------
// Softmax segment predictor: one warp per node.
// logits = x @ W + b ; S = softmax(logits, axis=1)
// ---------------------------------------------------------------------------
__global__ void softmax_kernel(const float* __restrict__ x,
                               const float* __restrict__ W,
                               const float* __restrict__ b,
                               float* __restrict__ S_out /* may be null */) {
    __shared__ float sW[D_FEAT * K_SEG];
    __shared__ float sb[K_SEG];
    const int tid = threadIdx.x;
    for (int i = tid; i < D_FEAT * K_SEG; i += blockDim.x) sW[i] = W[i];
    if (tid < K_SEG) sb[tid] = b[tid];
    __syncthreads();

    const int lane   = tid & 31;
    const int gwarp  = (blockIdx.x * blockDim.x + tid) >> 5;
    const int nwarps = (gridDim.x * blockDim.x) >> 5;

    for (int node = gwarp; node < N_NODES; node += nwarps) {
        // lane owns features [4*lane, 4*lane+3]
        const float4 xv = ((const float4*)(x + (size_t)node * D_FEAT))[lane];
        float acc[K_SEG];
        #pragma unroll
        for (int k = 0; k < K_SEG; k++) acc[k] = 0.0f;

        const float xd[4] = {xv.x, xv.y, xv.z, xv.w};
        #pragma unroll
        for (int j = 0; j < 4; j++) {
            const int d = 4 * lane + j;
            const float v = xd[j];
            #pragma unroll
            for (int k = 0; k < K_SEG; k++)
                acc[k] += v * sW[d * K_SEG + k];
        }
        // full butterfly: every lane ends with all 16 sums
        #pragma unroll
        for (int off = 16; off > 0; off >>= 1) {
            #pragma unroll
            for (int k = 0; k < K_SEG; k++)
                acc[k] += __shfl_xor_sync(0xffffffffu, acc[k], off);
        }

        if (lane == 0) {
            float logit[K_SEG];
            float mx = -1e30f;
            #pragma unroll
            for (int k = 0; k < K_SEG; k++) {
                logit[k] = acc[k] + sb[k];
                mx = fmaxf(mx, logit[k]);
            }
            float sum = 0.0f;
            #pragma unroll
            for (int k = 0; k < K_SEG; k++) {
                logit[k] = __expf(logit[k] - mx);
                sum += logit[k];
            }
            const float inv = 1.0f / sum;
            float* gs = g_S + (size_t)node * K_SEG;
            #pragma unroll
            for (int k = 0; k < K_SEG; k++) {
                const float s = logit[k] * inv;
                gs[k] = s;
                if (S_out) S_out[(size_t)node * K_SEG + k] = s;
            }
        }
    }
}

// ---------------------------------------------------------------------------
// Edge pass: warp per edge (contiguous chunks per warp).
//   w = exp(-||x_s - x_t||^2 / 2)
//   assoc[k] += w * S_s[k]
//   m[k]     += w * S_s[k] * S_t[k]
// Deterministic block reduction into g_partial.
// ---------------------------------------------------------------------------
__global__ void __launch_bounds__(EDGE_THREADS)
edge_kernel(const float* __restrict__ x, const void* __restrict__ ei_raw) {
    const int tid   = threadIdx.x;
    const int lane  = tid & 31;
    const int wib   = tid >> 5;                                   // warp in block
    const int gwarp = blockIdx.x * EDGE_WARPS_PER_BLOCK + wib;

    const int is64 = g_idx_is64;
    const long long* ei64 = (const long long*)ei_raw;
    const int*       ei32 = (const int*)ei_raw;

    const int per_warp = (E_EDGES + TOTAL_EDGE_WARPS - 1) / TOTAL_EDGE_WARPS;
    const int e0 = gwarp * per_warp;
    const int e1 = (e0 + per_warp < E_EDGES) ? (e0 + per_warp) : E_EDGES;

    float acc_a = 0.0f, acc_m = 0.0f;  // lane k<16 owns segment k

    for (int e = e0; e < e1; e++) {
        int src, tgt;
        if (is64) {
            src = (int)ei64[e];
            tgt = (int)ei64[E_EDGES + e];
        } else {
            src = ei32[e];
            tgt = ei32[E_EDGES + e];
        }
        const float4 a = ((const float4*)(x + (size_t)src * D_FEAT))[lane];
        const float4 c = ((const float4*)(x + (size_t)tgt * D_FEAT))[lane];
        const float dx = a.x - c.x, dy = a.y - c.y, dz = a.z - c.z, dw = a.w - c.w;
        float d = dx * dx + dy * dy;
        d = fmaf(dz, dz, d);
        d = fmaf(dw, dw, d);
        #pragma unroll
        for (int off = 16; off > 0; off >>= 1)
            d += __shfl_xor_sync(0xffffffffu, d, off);

        const float w = __expf(-0.5f * d);

        if (lane < K_SEG) {
            const float ss = g_S[(size_t)src * K_SEG + lane];
            const float st = g_S[(size_t)tgt * K_SEG + lane];
            acc_a = fmaf(w, ss, acc_a);
            acc_m = fmaf(w * ss, st, acc_m);
        }
    }

    // deterministic reduction: per-warp slots, warp 0 sums in fixed order
    __shared__ float red[EDGE_WARPS_PER_BLOCK][2 * K_SEG];
    if (lane < K_SEG) {
        red[wib][lane]         = acc_a;
        red[wib][K_SEG + lane] = acc_m;
    }
    __syncthreads();
    if (tid < 2 * K_SEG) {
        float sum = 0.0f;
        #pragma unroll
        for (int w2 = 0; w2 < EDGE_WARPS_PER_BLOCK; w2++)
            sum += red[w2][tid];
        g_partial[blockIdx.x * (2 * K_SEG) + tid] = sum;
    }
}

// ---------------------------------------------------------------------------
// Final: reduce partials, loss = sum_k where(assoc>eps, (assoc-m)/assoc, 0)
// ---------------------------------------------------------------------------
__global__ void final_kernel(float* __restrict__ loss_out) {
    __shared__ float s[2 * K_SEG];
    const int t = threadIdx.x;
    if (t < 2 * K_SEG) {
        float sum = 0.0f;
        for (int blk = 0; blk < EDGE_BLOCKS; blk++)
            sum += g_partial[blk * (2 * K_SEG) + t];
        s[t] = sum;
    }
    __syncthreads();
    if (t == 0) {
        float loss = 0.0f;
        #pragma unroll
        for (int k = 0; k < K_SEG; k++) {
            const float assoc = s[k];
            const float cut   = assoc - s[K_SEG + k];
            if (assoc > 1e-8f) loss += cut / assoc;
        }
        if (loss_out) *loss_out = loss;
    }
}

// ---------------------------------------------------------------------------
extern "C" void kernel_launch(void* const* d_in, const int* in_sizes, int n_in,
                              void* d_out, int out_size) {
    const float* x  = nullptr;
    const void*  ei = nullptr;
    const float* W  = nullptr;
    const float* b  = nullptr;

    for (int i = 0; i < n_in; i++) {
        const int s = in_sizes[i];
        if (s == N_NODES * D_FEAT) {
            // x is 6.4M floats; an int64 edge buffer miscounted as 4B units
            // would also be 6.4M — first match is x, second goes to edges.
            if (!x) x = (const float*)d_in[i];
            else if (!ei) ei = d_in[i];
        } else if (s == 2 * E_EDGES) {
            if (!ei) ei = d_in[i];
        } else if (s == D_FEAT * K_SEG) {
            W = (const float*)d_in[i];
        } else if (s == K_SEG) {
            b = (const float*)d_in[i];
        }
        // scalar num_expected_segments (size 1) intentionally ignored
    }

    // Output layout: tuple (loss, S) flattened -> [loss, S...]; or loss-only / S-only
    float* loss_out = nullptr;
    float* S_out    = nullptr;
    if (out_size == 1) {
        loss_out = (float*)d_out;
    } else if (out_size == N_NODES * K_SEG) {
        S_out = (float*)d_out;
    } else {
        loss_out = (float*)d_out;
        S_out    = (float*)d_out + 1;
    }

    detect_idx_kernel<<<1, 1>>>(ei);
    softmax_kernel<<<512, 256>>>(x, W, b, S_out);
    edge_kernel<<<EDGE_BLOCKS, EDGE_THREADS>>>(x, ei);
    final_kernel<<<1, 32>>>(loss_out);
}

// round 2
// speedup vs baseline: 1.3722x; 1.3722x over previous
#include <cuda_runtime.h>
#include <cuda_fp16.h>

#define N_NODES 50000
#define E_EDGES 1600000
#define D_FEAT  128
#define K_SEG   16

#define EDGE_BLOCKS 1250
#define EDGE_THREADS 256
#define EDGE_WARPS_PER_BLOCK (EDGE_THREADS / 32)
#define TOTAL_EDGE_WARPS (EDGE_BLOCKS * EDGE_WARPS_PER_BLOCK)   // 10000
#define EDGES_PER_WARP (E_EDGES / TOTAL_EDGE_WARPS)             // 160 (exact)

// Scratch (no allocations allowed in kernel_launch)
__device__ __half g_xh[N_NODES * D_FEAT];              // fp16 copy of x
__device__ float  g_S[N_NODES * K_SEG];                // softmax probabilities (fp32)
__device__ int    g_idx_is64;                          // 1 if edge_index is int64
__device__ float  g_partial[EDGE_BLOCKS * 2 * K_SEG];  // per-block [assoc(16), m(16)]

// ---------------------------------------------------------------------------
// Detect edge-index dtype (parallel: 64 lanes, one ballot).
// int32 data read as int64 -> hi word = next index (nonzero w.h.p.) -> huge.
// ---------------------------------------------------------------------------
__global__ void detect_idx_kernel(const void* __restrict__ ei_raw) {
    const long long* p = (const long long*)ei_raw;
    const int t = threadIdx.x;                 // 64 threads
    const long long v = p[t];
    const int bad = (v < 0 || v >= (long long)N_NODES) ? 1 : 0;
    __shared__ int any_bad;
    if (t == 0) any_bad = 0;
    __syncthreads();
    if (bad) atomicOr(&any_bad, 1);
    __syncthreads();
    if (t == 0) g_idx_is64 = any_bad ? 0 : 1;
}

// ---------------------------------------------------------------------------
// Softmax segment predictor: one warp per node.
// Also writes the fp16 copy of x (x row is already in registers).
// ---------------------------------------------------------------------------
__global__ void softmax_kernel(const float* __restrict__ x,
                               const float* __restrict__ W,
                               const float* __restrict__ b,
                               float* __restrict__ S_out /* may be null */) {
    __shared__ float sW[D_FEAT * K_SEG];
    __shared__ float sb[K_SEG];
    const int tid = threadIdx.x;
    for (int i = tid; i < D_FEAT * K_SEG; i += blockDim.x) sW[i] = W[i];
    if (tid < K_SEG) sb[tid] = b[tid];
    __syncthreads();

    const int lane   = tid & 31;
    const int gwarp  = (blockIdx.x * blockDim.x + tid) >> 5;
    const int nwarps = (gridDim.x * blockDim.x) >> 5;

    for (int node = gwarp; node < N_NODES; node += nwarps) {
        // lane owns features [4*lane, 4*lane+3]
        const float4 xv = ((const float4*)(x + (size_t)node * D_FEAT))[lane];

        // fp16 copy (two half2 per lane = 8 bytes, coalesced)
        {
            __half2 h0 = __floats2half2_rn(xv.x, xv.y);
            __half2 h1 = __floats2half2_rn(xv.z, xv.w);
            __half2* dst = (__half2*)(g_xh + (size_t)node * D_FEAT) + 2 * lane;
            dst[0] = h0;
            dst[1] = h1;
        }

        float acc[K_SEG];
        #pragma unroll
        for (int k = 0; k < K_SEG; k++) acc[k] = 0.0f;

        const float xd[4] = {xv.x, xv.y, xv.z, xv.w};
        #pragma unroll
        for (int j = 0; j < 4; j++) {
            const int d = 4 * lane + j;
            const float v = xd[j];
            #pragma unroll
            for (int k = 0; k < K_SEG; k++)
                acc[k] += v * sW[d * K_SEG + k];
        }
        #pragma unroll
        for (int off = 16; off > 0; off >>= 1) {
            #pragma unroll
            for (int k = 0; k < K_SEG; k++)
                acc[k] += __shfl_xor_sync(0xffffffffu, acc[k], off);
        }

        if (lane == 0) {
            float logit[K_SEG];
            float mx = -1e30f;
            #pragma unroll
            for (int k = 0; k < K_SEG; k++) {
                logit[k] = acc[k] + sb[k];
                mx = fmaxf(mx, logit[k]);
            }
            float sum = 0.0f;
            #pragma unroll
            for (int k = 0; k < K_SEG; k++) {
                logit[k] = __expf(logit[k] - mx);
                sum += logit[k];
            }
            const float inv = 1.0f / sum;
            float* gs = g_S + (size_t)node * K_SEG;
            #pragma unroll
            for (int k = 0; k < K_SEG; k++) {
                const float s = logit[k] * inv;
                gs[k] = s;
                if (S_out) S_out[(size_t)node * K_SEG + k] = s;
            }
        }
    }
}

// ---------------------------------------------------------------------------
// Edge pass: HALF-WARP per edge on fp16 x rows (256B per row, one sector set).
//   w = exp(-||x_s - x_t||^2 / 2)
//   assoc[k] += w * S_s[k] ; m[k] += w * S_s[k] * S_t[k]
// Deterministic block reduction into g_partial.
// ---------------------------------------------------------------------------
__global__ void __launch_bounds__(EDGE_THREADS)
edge_kernel(const void* __restrict__ ei_raw) {
    const int tid   = threadIdx.x;
    const int lane  = tid & 31;
    const int sub   = lane >> 4;     // which edge of the pair this half-warp owns
    const int l     = lane & 15;     // lane within half-warp (also segment id)
    const int wib   = tid >> 5;
    const int gwarp = blockIdx.x * EDGE_WARPS_PER_BLOCK + wib;

    const int is64 = g_idx_is64;
    const long long* ei64 = (const long long*)ei_raw;
    const int*       ei32 = (const int*)ei_raw;

    const int e0 = gwarp * EDGES_PER_WARP;

    float acc_a = 0.0f, acc_m = 0.0f;

    #pragma unroll 1
    for (int it = 0; it < EDGES_PER_WARP; it += 2) {
        const int e = e0 + it + sub;
        int src, tgt;
        if (is64) {
            src = (int)ei64[e];
            tgt = (int)ei64[E_EDGES + e];
        } else {
            src = ei32[e];
            tgt = ei32[E_EDGES + e];
        }

        // 16 lanes x 16B = full 256B fp16 row per edge
        const uint4 av = ((const uint4*)(g_xh + (size_t)src * D_FEAT))[l];
        const uint4 bv = ((const uint4*)(g_xh + (size_t)tgt * D_FEAT))[l];
        const __half2* ah = (const __half2*)&av;
        const __half2* bh = (const __half2*)&bv;

        float d = 0.0f;
        #pragma unroll
        for (int j = 0; j < 4; j++) {
            const float2 fa = __half22float2(ah[j]);
            const float2 fb = __half22float2(bh[j]);
            const float dx = fa.x - fb.x;
            const float dy = fa.y - fb.y;
            d = fmaf(dx, dx, d);
            d = fmaf(dy, dy, d);
        }
        // reduce across the 16-lane group (xor offsets < 16 stay in-group)
        d += __shfl_xor_sync(0xffffffffu, d, 8);
        d += __shfl_xor_sync(0xffffffffu, d, 4);
        d += __shfl_xor_sync(0xffffffffu, d, 2);
        d += __shfl_xor_sync(0xffffffffu, d, 1);

        const float w = __expf(-0.5f * d);

        // lane l owns segment l for this half-warp's edge (fp32 S for accuracy)
        const float ss = __ldg(g_S + (size_t)src * K_SEG + l);
        const float st = __ldg(g_S + (size_t)tgt * K_SEG + l);
        acc_a = fmaf(w, ss, acc_a);
        acc_m = fmaf(w * ss, st, acc_m);
    }

    // combine the two half-warps' accumulators (same segment l)
    acc_a += __shfl_xor_sync(0xffffffffu, acc_a, 16);
    acc_m += __shfl_xor_sync(0xffffffffu, acc_m, 16);

    // deterministic block reduction: per-warp slots, fixed summation order
    __shared__ float red[EDGE_WARPS_PER_BLOCK][2 * K_SEG];
    if (lane < K_SEG) {
        red[wib][lane]         = acc_a;
        red[wib][K_SEG + lane] = acc_m;
    }
    __syncthreads();
    if (tid < 2 * K_SEG) {
        float sum = 0.0f;
        #pragma unroll
        for (int w2 = 0; w2 < EDGE_WARPS_PER_BLOCK; w2++)
            sum += red[w2][tid];
        g_partial[blockIdx.x * (2 * K_SEG) + tid] = sum;
    }
}

// ---------------------------------------------------------------------------
// Final: parallel partial reduction (deterministic), then loss.
// 1024 threads: column c = t&31, chunk = t>>5 (32 chunks over EDGE_BLOCKS).
// ---------------------------------------------------------------------------
__global__ void final_kernel(float* __restrict__ loss_out) {
    __shared__ float red[32][32 + 1];
    const int t = threadIdx.x;          // 1024
    const int col   = t & 31;
    const int chunk = t >> 5;           // 0..31
    const int per   = (EDGE_BLOCKS + 31) / 32;
    const int b0 = chunk * per;
    const int b1 = (b0 + per < EDGE_BLOCKS) ? (b0 + per) : EDGE_BLOCKS;

    float sum = 0.0f;
    for (int blk = b0; blk < b1; blk++)
        sum += g_partial[blk * (2 * K_SEG) + col];
    red[chunk][col] = sum;
    __syncthreads();

    if (t < 32) {
        float tot = 0.0f;
        #pragma unroll
        for (int c2 = 0; c2 < 32; c2++)
            tot += red[c2][t];
        red[32 - 1][t] = 0.0f;  // no-op keep shape
        __shared__ float s[2 * K_SEG];
        s[t] = tot;
        __syncwarp();
        if (t == 0) {
            float loss = 0.0f;
            #pragma unroll
            for (int k = 0; k < K_SEG; k++) {
                const float assoc = s[k];
                const float cut   = assoc - s[K_SEG + k];
                if (assoc > 1e-8f) loss += cut / assoc;
            }
            if (loss_out) *loss_out = loss;
        }
    }
}

// ---------------------------------------------------------------------------
extern "C" void kernel_launch(void* const* d_in, const int* in_sizes, int n_in,
                              void* d_out, int out_size) {
    const float* x  = nullptr;
    const void*  ei = nullptr;
    const float* W  = nullptr;
    const float* b  = nullptr;

    for (int i = 0; i < n_in; i++) {
        const int s = in_sizes[i];
        if (s == N_NODES * D_FEAT) {
            if (!x) x = (const float*)d_in[i];
            else if (!ei) ei = d_in[i];
        } else if (s == 2 * E_EDGES) {
            if (!ei) ei = d_in[i];
        } else if (s == D_FEAT * K_SEG) {
            W = (const float*)d_in[i];
        } else if (s == K_SEG) {
            b = (const float*)d_in[i];
        }
    }

    float* loss_out = nullptr;
    float* S_out    = nullptr;
    if (out_size == 1) {
        loss_out = (float*)d_out;
    } else if (out_size == N_NODES * K_SEG) {
        S_out = (float*)d_out;
    } else {
        loss_out = (float*)d_out;
        S_out    = (float*)d_out + 1;
    }

    detect_idx_kernel<<<1, 64>>>(ei);
    softmax_kernel<<<512, 256>>>(x, W, b, S_out);
    edge_kernel<<<EDGE_BLOCKS, EDGE_THREADS>>>(ei);
    final_kernel<<<1, 1024>>>(loss_out);
}

// round 3
// speedup vs baseline: 1.6453x; 1.1991x over previous
#include <cuda_runtime.h>
#include <cuda_fp16.h>

#define N_NODES 50000
#define E_EDGES 1600000
#define D_FEAT  128
#define K_SEG   16

#define EDGE_BLOCKS 1250
#define EDGE_THREADS 256
#define EDGE_WARPS_PER_BLOCK (EDGE_THREADS / 32)
#define TOTAL_EDGE_WARPS (EDGE_BLOCKS * EDGE_WARPS_PER_BLOCK)   // 10000
#define EDGES_PER_WARP (E_EDGES / TOTAL_EDGE_WARPS)             // 160 (exact)

#define X_SCALE 16.0f            // x scaled by 16 before fp8 e4m3 quantization
// dist on scaled values = 256 * dist ; w = exp(-dist/2) = exp(-dist_scaled/512)
#define W_EXP_COEF (-1.0f / 512.0f)

// Scratch (no allocations allowed in kernel_launch)
__device__ __align__(128) unsigned char g_x8[N_NODES * D_FEAT];   // fp8 e4m3 copy of 16*x
__device__ __align__(128) __half        g_Sh[N_NODES * K_SEG];    // fp16 copy of S
__device__ int          g_idx_is64;
__device__ unsigned int g_done;
__device__ float        g_partial[EDGE_BLOCKS * 2 * K_SEG];       // [assoc(16), m(16)] per block

// ---- fp8 helpers -----------------------------------------------------------
__device__ __forceinline__ unsigned short f32x2_to_e4m3x2(float a, float b) {
    unsigned short r;
    asm("cvt.rn.satfinite.e4m3x2.f32 %0, %1, %2;" : "=h"(r) : "f"(a), "f"(b));
    return r;
}
__device__ __forceinline__ __half2 e4m3x2_to_half2(unsigned short v) {
    unsigned int r;
    asm("cvt.rn.f16x2.e4m3x2 %0, %1;" : "=r"(r) : "h"(v));
    return *reinterpret_cast<__half2*>(&r);
}

// ---------------------------------------------------------------------------
// Detect edge-index dtype + reset completion counter.
// ---------------------------------------------------------------------------
__global__ void detect_idx_kernel(const void* __restrict__ ei_raw) {
    const long long* p = (const long long*)ei_raw;
    const int t = threadIdx.x;                 // 64 threads
    const long long v = p[t];
    const int bad = (v < 0 || v >= (long long)N_NODES) ? 1 : 0;
    __shared__ int any_bad;
    if (t == 0) { any_bad = 0; g_done = 0u; }
    __syncthreads();
    if (bad) atomicOr(&any_bad, 1);
    __syncthreads();
    if (t == 0) g_idx_is64 = any_bad ? 0 : 1;
}

// ---------------------------------------------------------------------------
// Softmax segment predictor: one warp per node.
// Writes fp32 S to S_out (if requested), fp16 S to g_Sh, fp8 x to g_x8.
// ---------------------------------------------------------------------------
__global__ void softmax_kernel(const float* __restrict__ x,
                               const float* __restrict__ W,
                               const float* __restrict__ b,
                               float* __restrict__ S_out /* may be null */) {
    __shared__ float sW[D_FEAT * K_SEG];
    __shared__ float sb[K_SEG];
    const int tid = threadIdx.x;
    for (int i = tid; i < D_FEAT * K_SEG; i += blockDim.x) sW[i] = W[i];
    if (tid < K_SEG) sb[tid] = b[tid];
    __syncthreads();

    const int lane   = tid & 31;
    const int gwarp  = (blockIdx.x * blockDim.x + tid) >> 5;
    const int nwarps = (gridDim.x * blockDim.x) >> 5;

    for (int node = gwarp; node < N_NODES; node += nwarps) {
        const float4 xv = ((const float4*)(x + (size_t)node * D_FEAT))[lane];

        // fp8 copy of 16*x (4B per lane, coalesced 128B row)
        {
            const unsigned short p0 = f32x2_to_e4m3x2(xv.y * X_SCALE, xv.x * X_SCALE);
            const unsigned short p1 = f32x2_to_e4m3x2(xv.w * X_SCALE, xv.z * X_SCALE);
            ((unsigned int*)(g_x8 + (size_t)node * D_FEAT))[lane] =
                (unsigned int)p0 | ((unsigned int)p1 << 16);
        }

        float acc[K_SEG];
        #pragma unroll
        for (int k = 0; k < K_SEG; k++) acc[k] = 0.0f;

        const float xd[4] = {xv.x, xv.y, xv.z, xv.w};
        #pragma unroll
        for (int j = 0; j < 4; j++) {
            const int d = 4 * lane + j;
            const float v = xd[j];
            #pragma unroll
            for (int k = 0; k < K_SEG; k++)
                acc[k] += v * sW[d * K_SEG + k];
        }
        #pragma unroll
        for (int off = 16; off > 0; off >>= 1) {
            #pragma unroll
            for (int k = 0; k < K_SEG; k++)
                acc[k] += __shfl_xor_sync(0xffffffffu, acc[k], off);
        }

        if (lane == 0) {
            float logit[K_SEG];
            float mx = -1e30f;
            #pragma unroll
            for (int k = 0; k < K_SEG; k++) {
                logit[k] = acc[k] + sb[k];
                mx = fmaxf(mx, logit[k]);
            }
            float sum = 0.0f;
            #pragma unroll
            for (int k = 0; k < K_SEG; k++) {
                logit[k] = __expf(logit[k] - mx);
                sum += logit[k];
            }
            const float inv = 1.0f / sum;
            float sval[K_SEG];
            #pragma unroll
            for (int k = 0; k < K_SEG; k++) sval[k] = logit[k] * inv;

            if (S_out) {
                #pragma unroll
                for (int k = 0; k < K_SEG; k++)
                    S_out[(size_t)node * K_SEG + k] = sval[k];
            }
            __half2* sh = (__half2*)(g_Sh + (size_t)node * K_SEG);
            #pragma unroll
            for (int k = 0; k < K_SEG / 2; k++)
                sh[k] = __floats2half2_rn(sval[2 * k], sval[2 * k + 1]);
        }
    }
}

// ---------------------------------------------------------------------------
// Edge pass: QUARTER-WARP per edge on fp8 x rows (128B/row = 8 lanes x uint4).
//   w = exp(-||x_s - x_t||^2 / 2)
//   assoc[k] += w * S_s[k] ; m[k] += w * S_s[k] * S_t[k]
// Lane l of each 8-lane group owns segments (2l, 2l+1) via half2 S loads.
// Last block performs the global reduction + loss (threadfence pattern).
// ---------------------------------------------------------------------------
__global__ void __launch_bounds__(EDGE_THREADS)
edge_kernel(const void* __restrict__ ei_raw, float* __restrict__ loss_out) {
    const int tid   = threadIdx.x;
    const int lane  = tid & 31;
    const int sub   = lane >> 3;     // 0..3: which edge of the quad
    const int l     = lane & 7;      // lane within quarter-warp
    const int wib   = tid >> 5;
    const int gwarp = blockIdx.x * EDGE_WARPS_PER_BLOCK + wib;

    const int is64 = g_idx_is64;
    const long long* ei64 = (const long long*)ei_raw;
    const int*       ei32 = (const int*)ei_raw;

    const int e0 = gwarp * EDGES_PER_WARP;

    float2 acc_a = make_float2(0.0f, 0.0f);   // segments (2l, 2l+1)
    float2 acc_m = make_float2(0.0f, 0.0f);

    #pragma unroll 1
    for (int it = 0; it < EDGES_PER_WARP; it += 4) {
        const int e = e0 + it + sub;
        int src, tgt;
        if (is64) {
            src = (int)ei64[e];
            tgt = (int)ei64[E_EDGES + e];
        } else {
            src = ei32[e];
            tgt = ei32[E_EDGES + e];
        }

        // 8 lanes x 16B = full 128B fp8 row per edge
        const uint4 av = ((const uint4*)(g_x8 + (size_t)src * D_FEAT))[l];
        const uint4 bv = ((const uint4*)(g_x8 + (size_t)tgt * D_FEAT))[l];
        const unsigned short* ap = (const unsigned short*)&av;
        const unsigned short* bp = (const unsigned short*)&bv;

        __half2 dacc = __floats2half2_rn(0.0f, 0.0f);
        #pragma unroll
        for (int j = 0; j < 8; j++) {
            const __half2 ha = e4m3x2_to_half2(ap[j]);
            const __half2 hb = e4m3x2_to_half2(bp[j]);
            const __half2 dh = __hsub2(ha, hb);
            dacc = __hfma2(dh, dh, dacc);
        }
        float d = __low2float(dacc) + __high2float(dacc);
        // reduce across the 8-lane group
        d += __shfl_xor_sync(0xffffffffu, d, 4);
        d += __shfl_xor_sync(0xffffffffu, d, 2);
        d += __shfl_xor_sync(0xffffffffu, d, 1);

        const float w = __expf(d * W_EXP_COEF);

        // fp16 S rows: 8 lanes x half2 = 32B per row
        const __half2 sh = ((const __half2*)(g_Sh + (size_t)src * K_SEG))[l];
        const __half2 th = ((const __half2*)(g_Sh + (size_t)tgt * K_SEG))[l];
        const float2 fs = __half22float2(sh);
        const float2 ft = __half22float2(th);
        acc_a.x = fmaf(w, fs.x, acc_a.x);
        acc_a.y = fmaf(w, fs.y, acc_a.y);
        acc_m.x = fmaf(w * fs.x, ft.x, acc_m.x);
        acc_m.y = fmaf(w * fs.y, ft.y, acc_m.y);
    }

    // combine the four quarter-warps (same segment mapping per l)
    #pragma unroll
    for (int off = 8; off < 32; off <<= 1) {
        acc_a.x += __shfl_xor_sync(0xffffffffu, acc_a.x, off);
        acc_a.y += __shfl_xor_sync(0xffffffffu, acc_a.y, off);
        acc_m.x += __shfl_xor_sync(0xffffffffu, acc_m.x, off);
        acc_m.y += __shfl_xor_sync(0xffffffffu, acc_m.y, off);
    }

    // deterministic block reduction
    __shared__ float red[EDGE_WARPS_PER_BLOCK][2 * K_SEG];
    if (lane < 8) {
        red[wib][2 * l]             = acc_a.x;
        red[wib][2 * l + 1]         = acc_a.y;
        red[wib][K_SEG + 2 * l]     = acc_m.x;
        red[wib][K_SEG + 2 * l + 1] = acc_m.y;
    }
    __syncthreads();
    if (tid < 2 * K_SEG) {
        float sum = 0.0f;
        #pragma unroll
        for (int w2 = 0; w2 < EDGE_WARPS_PER_BLOCK; w2++)
            sum += red[w2][tid];
        g_partial[blockIdx.x * (2 * K_SEG) + tid] = sum;
    }

    // last-block global reduction
    __shared__ unsigned int s_ticket;
    __threadfence();
    __syncthreads();
    if (tid == 0) s_ticket = atomicAdd(&g_done, 1u);
    __syncthreads();
    if (s_ticket == EDGE_BLOCKS - 1) {
        __threadfence();
        // 256 threads: col = tid&31, chunk = tid>>5 (8 chunks, fixed order)
        __shared__ float cred[EDGE_THREADS / 32][32];
        const int col   = tid & 31;
        const int chunk = tid >> 5;
        const int per   = (EDGE_BLOCKS + 7) / 8;
        const int b0 = chunk * per;
        const int b1 = (b0 + per < EDGE_BLOCKS) ? (b0 + per) : EDGE_BLOCKS;
        float sum = 0.0f;
        for (int blk = b0; blk < b1; blk++)
            sum += g_partial[blk * (2 * K_SEG) + col];
        cred[chunk][col] = sum;
        __syncthreads();
        if (tid == 0 && loss_out) {
            float tot[2 * K_SEG];
            #pragma unroll
            for (int c = 0; c < 2 * K_SEG; c++) {
                float t = 0.0f;
                #pragma unroll
                for (int ch = 0; ch < EDGE_THREADS / 32; ch++)
                    t += cred[ch][c];
                tot[c] = t;
            }
            float loss = 0.0f;
            #pragma unroll
            for (int k = 0; k < K_SEG; k++) {
                const float assoc = tot[k];
                const float cut   = assoc - tot[K_SEG + k];
                if (assoc > 1e-8f) loss += cut / assoc;
            }
            *loss_out = loss;
        }
    }
}

// ---------------------------------------------------------------------------
extern "C" void kernel_launch(void* const* d_in, const int* in_sizes, int n_in,
                              void* d_out, int out_size) {
    const float* x  = nullptr;
    const void*  ei = nullptr;
    const float* W  = nullptr;
    const float* b  = nullptr;

    for (int i = 0; i < n_in; i++) {
        const int s = in_sizes[i];
        if (s == N_NODES * D_FEAT) {
            if (!x) x = (const float*)d_in[i];
            else if (!ei) ei = d_in[i];
        } else if (s == 2 * E_EDGES) {
            if (!ei) ei = d_in[i];
        } else if (s == D_FEAT * K_SEG) {
            W = (const float*)d_in[i];
        } else if (s == K_SEG) {
            b = (const float*)d_in[i];
        }
    }

    float* loss_out = nullptr;
    float* S_out    = nullptr;
    if (out_size == 1) {
        loss_out = (float*)d_out;
    } else if (out_size == N_NODES * K_SEG) {
        S_out = (float*)d_out;
    } else {
        loss_out = (float*)d_out;
        S_out    = (float*)d_out + 1;
    }

    detect_idx_kernel<<<1, 64>>>(ei);
    softmax_kernel<<<512, 256>>>(x, W, b, S_out);
    edge_kernel<<<EDGE_BLOCKS, EDGE_THREADS>>>(ei, loss_out);
}

// round 4
// speedup vs baseline: 2.3150x; 1.4070x over previous
#include <cuda_runtime.h>
#include <cuda_fp16.h>

#define N_NODES 50000
#define E_EDGES 1600000
#define D_FEAT  128
#define K_SEG   16

#define EDGE_BLOCKS 1250
#define EDGE_THREADS 256
#define EDGE_WARPS_PER_BLOCK (EDGE_THREADS / 32)
#define TOTAL_EDGE_WARPS (EDGE_BLOCKS * EDGE_WARPS_PER_BLOCK)   // 10000
#define EDGES_PER_WARP (E_EDGES / TOTAL_EDGE_WARPS)             // 160 (exact)

#define X_SCALE 16.0f            // x scaled by 16 before fp8 e4m3 quantization
// dist on scaled values = 256 * dist ; w = exp(-dist/2) = exp(-dist_scaled/512)
#define W_EXP_COEF (-1.0f / 512.0f)

// Scratch (no allocations allowed in kernel_launch)
__device__ __align__(128) unsigned char g_x8[N_NODES * D_FEAT];   // fp8 e4m3 copy of 16*x
__device__ __align__(128) __half        g_Sh[N_NODES * K_SEG];    // fp16 copy of S
__device__ unsigned int g_done = 0;                               // reset by last block
__device__ float        g_partial[EDGE_BLOCKS * 2 * K_SEG];       // [assoc(16), m(16)] per block

// ---- fp8 helpers -----------------------------------------------------------
__device__ __forceinline__ unsigned short f32x2_to_e4m3x2(float a, float b) {
    unsigned short r;
    asm("cvt.rn.satfinite.e4m3x2.f32 %0, %1, %2;" : "=h"(r) : "f"(a), "f"(b));
    return r;
}
__device__ __forceinline__ __half2 e4m3x2_to_half2(unsigned short v) {
    unsigned int r;
    asm("cvt.rn.f16x2.e4m3x2 %0, %1;" : "=r"(r) : "h"(v));
    return *reinterpret_cast<__half2*>(&r);
}

// ---------------------------------------------------------------------------
// Softmax segment predictor: one warp per node, conflict-free transposed W,
// decimated warp reduction (lane ends holding segment k = lane>>1).
// Writes fp32 S to S_out (if requested), fp16 S to g_Sh, fp8 x to g_x8.
// ---------------------------------------------------------------------------
__global__ void softmax_kernel(const float* __restrict__ x,
                               const float* __restrict__ W,
                               const float* __restrict__ b,
                               float* __restrict__ S_out /* may be null */) {
    __shared__ float sWT[K_SEG][D_FEAT];   // transposed: [k][d]
    __shared__ float sb[K_SEG];
    const int tid = threadIdx.x;
    for (int i = tid; i < D_FEAT * K_SEG; i += blockDim.x) {
        const int d = i >> 4;      // W is [D][K] row-major
        const int k = i & 15;
        sWT[k][d] = W[i];
    }
    if (tid < K_SEG) sb[tid] = b[tid];
    __syncthreads();

    const int lane   = tid & 31;
    const int gwarp  = (blockIdx.x * blockDim.x + tid) >> 5;
    const int nwarps = (gridDim.x * blockDim.x) >> 5;

    for (int node = gwarp; node < N_NODES; node += nwarps) {
        const float4 xv = ((const float4*)(x + (size_t)node * D_FEAT))[lane];

        // fp8 copy of 16*x (4B per lane, coalesced 128B row)
        {
            const unsigned short p0 = f32x2_to_e4m3x2(xv.y * X_SCALE, xv.x * X_SCALE);
            const unsigned short p1 = f32x2_to_e4m3x2(xv.w * X_SCALE, xv.z * X_SCALE);
            ((unsigned int*)(g_x8 + (size_t)node * D_FEAT))[lane] =
                (unsigned int)p0 | ((unsigned int)p1 << 16);
        }

        // per-lane partial dot for all 16 segments (LDS.128, conflict-free)
        float v[K_SEG];
        #pragma unroll
        for (int k = 0; k < K_SEG; k++) {
            const float4 wv = ((const float4*)sWT[k])[lane];
            v[k] = xv.x * wv.x + xv.y * wv.y + xv.z * wv.z + xv.w * wv.w;
        }

        // decimated exchange reduction: 8+4+2+1+1 shfl
        {
            const bool hi = (lane & 16) != 0;
            #pragma unroll
            for (int k = 0; k < 8; k++) {
                const float send = hi ? v[k] : v[k + 8];
                const float keep = hi ? v[k + 8] : v[k];
                v[k] = keep + __shfl_xor_sync(0xffffffffu, send, 16);
            }
        }
        {
            const bool hi = (lane & 8) != 0;
            #pragma unroll
            for (int k = 0; k < 4; k++) {
                const float send = hi ? v[k] : v[k + 4];
                const float keep = hi ? v[k + 4] : v[k];
                v[k] = keep + __shfl_xor_sync(0xffffffffu, send, 8);
            }
        }
        {
            const bool hi = (lane & 4) != 0;
            #pragma unroll
            for (int k = 0; k < 2; k++) {
                const float send = hi ? v[k] : v[k + 2];
                const float keep = hi ? v[k + 2] : v[k];
                v[k] = keep + __shfl_xor_sync(0xffffffffu, send, 4);
            }
        }
        {
            const bool hi = (lane & 2) != 0;
            const float send = hi ? v[0] : v[1];
            const float keep = hi ? v[1] : v[0];
            v[0] = keep + __shfl_xor_sync(0xffffffffu, send, 2);
        }
        v[0] += __shfl_xor_sync(0xffffffffu, v[0], 1);
        // lane now holds full logit-sum for segment k = lane>>1 (pairs duplicated)
        const int kseg = lane >> 1;

        const float logit = v[0] + sb[kseg];
        // warp softmax over the 16 distinct segments (duplicates are consistent)
        float mx = logit;
        #pragma unroll
        for (int off = 16; off > 0; off >>= 1)
            mx = fmaxf(mx, __shfl_xor_sync(0xffffffffu, mx, off));
        const float e = __expf(logit - mx);
        float sum = e;
        #pragma unroll
        for (int off = 16; off > 1; off >>= 1)       // off=1 pair holds same k: skip
            sum += __shfl_xor_sync(0xffffffffu, sum, off);
        sum += __shfl_xor_sync(0xffffffffu, sum, 1); // now includes duplicate -> sum is 2x
        const float s = e * 2.0f / sum;

        if ((lane & 1) == 0) {
            g_Sh[(size_t)node * K_SEG + kseg] = __float2half_rn(s);
            if (S_out) S_out[(size_t)node * K_SEG + kseg] = s;
        }
    }
}

// ---------------------------------------------------------------------------
// Edge pass: QUARTER-WARP per edge on fp8 x rows (128B/row = 8 lanes x uint4).
//   w = exp(-||x_s - x_t||^2 / 2)
//   assoc[k] += w * S_s[k] ; m[k] += w * S_s[k] * S_t[k]
// Lane l of each 8-lane group owns segments (2l, 2l+1) via half2 S loads.
// Detect of index dtype is fused (per-block, deterministic).
// Last block performs the global reduction + loss and resets g_done.
// ---------------------------------------------------------------------------
__global__ void __launch_bounds__(EDGE_THREADS)
edge_kernel(const void* __restrict__ ei_raw, float* __restrict__ loss_out) {
    const int tid   = threadIdx.x;
    const int lane  = tid & 31;
    const int sub   = lane >> 3;     // 0..3: which edge of the quad
    const int l     = lane & 7;      // lane within quarter-warp
    const int wib   = tid >> 5;
    const int gwarp = blockIdx.x * EDGE_WARPS_PER_BLOCK + wib;

    // fused dtype detection: int32 read as int64 -> hi word = next index -> huge
    __shared__ int s_is64;
    if (tid == 0) s_is64 = 1;
    __syncthreads();
    if (tid < 64) {
        const long long vv = ((const long long*)ei_raw)[tid];
        if (vv < 0 || vv >= (long long)N_NODES) s_is64 = 0;  // benign racing writes of 0
    }
    __syncthreads();
    const int is64 = s_is64;

    const long long* ei64 = (const long long*)ei_raw;
    const int*       ei32 = (const int*)ei_raw;

    const int e0 = gwarp * EDGES_PER_WARP;

    float2 acc_a = make_float2(0.0f, 0.0f);   // segments (2l, 2l+1)
    float2 acc_m = make_float2(0.0f, 0.0f);

    #pragma unroll 2
    for (int it = 0; it < EDGES_PER_WARP; it += 4) {
        const int e = e0 + it + sub;
        int src, tgt;
        if (is64) {
            src = (int)ei64[e];
            tgt = (int)ei64[E_EDGES + e];
        } else {
            src = ei32[e];
            tgt = ei32[E_EDGES + e];
        }

        // 8 lanes x 16B = full 128B fp8 row per edge
        const uint4 av = ((const uint4*)(g_x8 + (size_t)src * D_FEAT))[l];
        const uint4 bv = ((const uint4*)(g_x8 + (size_t)tgt * D_FEAT))[l];
        const unsigned short* ap = (const unsigned short*)&av;
        const unsigned short* bp = (const unsigned short*)&bv;

        __half2 dacc = __floats2half2_rn(0.0f, 0.0f);
        #pragma unroll
        for (int j = 0; j < 8; j++) {
            const __half2 ha = e4m3x2_to_half2(ap[j]);
            const __half2 hb = e4m3x2_to_half2(bp[j]);
            const __half2 dh = __hsub2(ha, hb);
            dacc = __hfma2(dh, dh, dacc);
        }
        float d = __low2float(dacc) + __high2float(dacc);
        // reduce across the 8-lane group
        d += __shfl_xor_sync(0xffffffffu, d, 4);
        d += __shfl_xor_sync(0xffffffffu, d, 2);
        d += __shfl_xor_sync(0xffffffffu, d, 1);

        const float w = __expf(d * W_EXP_COEF);

        // fp16 S rows: 8 lanes x half2 = 32B per row
        const __half2 sh = ((const __half2*)(g_Sh + (size_t)src * K_SEG))[l];
        const __half2 th = ((const __half2*)(g_Sh + (size_t)tgt * K_SEG))[l];
        const float2 fs = __half22float2(sh);
        const float2 ft = __half22float2(th);
        acc_a.x = fmaf(w, fs.x, acc_a.x);
        acc_a.y = fmaf(w, fs.y, acc_a.y);
        acc_m.x = fmaf(w * fs.x, ft.x, acc_m.x);
        acc_m.y = fmaf(w * fs.y, ft.y, acc_m.y);
    }

    // combine the four quarter-warps (same segment mapping per l)
    #pragma unroll
    for (int off = 8; off < 32; off <<= 1) {
        acc_a.x += __shfl_xor_sync(0xffffffffu, acc_a.x, off);
        acc_a.y += __shfl_xor_sync(0xffffffffu, acc_a.y, off);
        acc_m.x += __shfl_xor_sync(0xffffffffu, acc_m.x, off);
        acc_m.y += __shfl_xor_sync(0xffffffffu, acc_m.y, off);
    }

    // deterministic block reduction
    __shared__ float red[EDGE_WARPS_PER_BLOCK][2 * K_SEG];
    if (lane < 8) {
        red[wib][2 * l]             = acc_a.x;
        red[wib][2 * l + 1]         = acc_a.y;
        red[wib][K_SEG + 2 * l]     = acc_m.x;
        red[wib][K_SEG + 2 * l + 1] = acc_m.y;
    }
    __syncthreads();
    if (tid < 2 * K_SEG) {
        float sum = 0.0f;
        #pragma unroll
        for (int w2 = 0; w2 < EDGE_WARPS_PER_BLOCK; w2++)
            sum += red[w2][tid];
        g_partial[blockIdx.x * (2 * K_SEG) + tid] = sum;
    }

    // last-block global reduction
    __shared__ unsigned int s_ticket;
    __threadfence();
    __syncthreads();
    if (tid == 0) s_ticket = atomicAdd(&g_done, 1u);
    __syncthreads();
    if (s_ticket == EDGE_BLOCKS - 1) {
        __threadfence();
        __shared__ float cred[EDGE_THREADS / 32][32];
        const int col   = tid & 31;
        const int chunk = tid >> 5;
        const int per   = (EDGE_BLOCKS + 7) / 8;
        const int b0 = chunk * per;
        const int b1 = (b0 + per < EDGE_BLOCKS) ? (b0 + per) : EDGE_BLOCKS;
        float sum = 0.0f;
        for (int blk = b0; blk < b1; blk++)
            sum += g_partial[blk * (2 * K_SEG) + col];
        cred[chunk][col] = sum;
        __syncthreads();
        if (tid == 0) {
            float tot[2 * K_SEG];
            #pragma unroll
            for (int c = 0; c < 2 * K_SEG; c++) {
                float t = 0.0f;
                #pragma unroll
                for (int ch = 0; ch < EDGE_THREADS / 32; ch++)
                    t += cred[ch][c];
                tot[c] = t;
            }
            float loss = 0.0f;
            #pragma unroll
            for (int k = 0; k < K_SEG; k++) {
                const float assoc = tot[k];
                const float cut   = assoc - tot[K_SEG + k];
                if (assoc > 1e-8f) loss += cut / assoc;
            }
            if (loss_out) *loss_out = loss;
            g_done = 0;   // reset for next graph replay
        }
    }
}

// ---------------------------------------------------------------------------
extern "C" void kernel_launch(void* const* d_in, const int* in_sizes, int n_in,
                              void* d_out, int out_size) {
    const float* x  = nullptr;
    const void*  ei = nullptr;
    const float* W  = nullptr;
    const float* b  = nullptr;

    for (int i = 0; i < n_in; i++) {
        const int s = in_sizes[i];
        if (s == N_NODES * D_FEAT) {
            if (!x) x = (const float*)d_in[i];
            else if (!ei) ei = d_in[i];
        } else if (s == 2 * E_EDGES) {
            if (!ei) ei = d_in[i];
        } else if (s == D_FEAT * K_SEG) {
            W = (const float*)d_in[i];
        } else if (s == K_SEG) {
            b = (const float*)d_in[i];
        }
    }

    float* loss_out = nullptr;
    float* S_out    = nullptr;
    if (out_size == 1) {
        loss_out = (float*)d_out;
    } else if (out_size == N_NODES * K_SEG) {
        S_out = (float*)d_out;
    } else {
        loss_out = (float*)d_out;
        S_out    = (float*)d_out + 1;
    }

    softmax_kernel<<<512, 256>>>(x, W, b, S_out);
    edge_kernel<<<EDGE_BLOCKS, EDGE_THREADS>>>(ei, loss_out);
}